// round 2
// baseline (speedup 1.0000x reference)
#include <cuda_runtime.h>
#include <math.h>

#define XS   256
#define BB   16
#define HALFK 129               // XS/2 + 1
#define NPIX (BB * XS * XS)

// ---------------- scratch (device globals: no allocation allowed) ----------
__device__ float  g_prep[BB * 16];      // per batch: R00..R12 (6), s0, s1, h[8]
__device__ float  g_gauss[7];
__device__ float  g_img[NPIX];          // scatter target / final blurred image
__device__ float  g_tmp[NPIX];          // blur intermediate
__device__ float2 g_A[BB * XS * HALFK]; // half-spectrum

// ---------------- zero image ----------------
__global__ void zero_kernel() {
    int i = blockIdx.x * blockDim.x + threadIdx.x;
    float4* p = (float4*)g_img;
    if (i < NPIX / 4) p[i] = make_float4(0.f, 0.f, 0.f, 0.f);
}

// ---------------- prep: rotations + SIREN head + gaussian taps -------------
// Rotation entries computed with EXPLICIT mul/add/sub (no fma contraction),
// left-associated exactly like the reference's elementwise expressions.
__global__ void prep_kernel(const float* __restrict__ rows,
                            const float* __restrict__ shifts,
                            const float* __restrict__ latent,
                            const float* __restrict__ W0, const float* __restrict__ b0,
                            const float* __restrict__ W1, const float* __restrict__ b1,
                            const float* __restrict__ W2, const float* __restrict__ b2,
                            const float* __restrict__ W3, const float* __restrict__ b3) {
    int b = threadIdx.x;
    if (b < BB) {
        float rot = rows[b*3+0], tilt = rows[b*3+1], psi = rows[b*3+2];
        float ca = cosf(rot),  sa = sinf(rot);
        float cb = cosf(tilt), sb = sinf(tilt);
        float cg = cosf(psi),  sg = sinf(psi);
        float nsg = -sg;
        float* p = &g_prep[b * 16];
        // row 0:  cg*cb*ca - sg*sa,  cg*cb*sa + sg*ca,  -cg*sb
        p[0] = __fsub_rn(__fmul_rn(__fmul_rn(cg, cb), ca), __fmul_rn(sg, sa));
        p[1] = __fadd_rn(__fmul_rn(__fmul_rn(cg, cb), sa), __fmul_rn(sg, ca));
        p[2] = -__fmul_rn(cg, sb);
        // row 1: -sg*cb*ca - cg*sa, -sg*cb*sa + cg*ca,   sg*sb
        p[3] = __fsub_rn(__fmul_rn(__fmul_rn(nsg, cb), ca), __fmul_rn(cg, sa));
        p[4] = __fadd_rn(__fmul_rn(__fmul_rn(nsg, cb), sa), __fmul_rn(cg, ca));
        p[5] = __fmul_rn(sg, sb);
        p[6] = shifts[b*2+0];
        p[7] = shifts[b*2+1];

        float h[8];
        #pragma unroll
        for (int j = 0; j < 8; j++) {
            float acc = b0[j];
            #pragma unroll
            for (int l = 0; l < 8; l++) acc += latent[b*8+l] * W0[l*8+j];
            h[j] = sinf(30.0f * acc);
        }
        const float* Ws[3] = {W1, W2, W3};
        const float* bs[3] = {b1, b2, b3};
        for (int s = 0; s < 3; s++) {
            float t[8];
            #pragma unroll
            for (int j = 0; j < 8; j++) {
                float acc = bs[s][j];
                #pragma unroll
                for (int l = 0; l < 8; l++) acc += h[l] * Ws[s][l*8+j];
                t[j] = sinf(acc);
            }
            #pragma unroll
            for (int j = 0; j < 8; j++) h[j] += t[j];
        }
        #pragma unroll
        for (int j = 0; j < 8; j++) p[8+j] = h[j];
    }
    if (threadIdx.x == 0) {
        float k[7], s = 0.f;
        for (int i = 0; i < 7; i++) { float x = (float)(i - 3); k[i] = expf(-0.5f * x * x); s += k[i]; }
        for (int i = 0; i < 7; i++) g_gauss[i] = k[i] / s;
    }
}

// ---------------- scatter: one thread per point, loop over batches ----------
// Rotation dot and the +shift+half chain use explicit rounding-controlled
// operations matching the reference (GEMM ascending-K fma; left-assoc adds).
__global__ void scatter_kernel(const float* __restrict__ coords,
                               const float* __restrict__ values,
                               const float* __restrict__ Wd,
                               const float* __restrict__ bd,
                               int N) {
    __shared__ float sp[256];  // 16 batches x 16 floats
    if (threadIdx.x < 256) sp[threadIdx.x] = g_prep[threadIdx.x];
    __syncthreads();

    int n = blockIdx.x * blockDim.x + threadIdx.x;
    if (n >= N) return;

    float cx = coords[n*3+0], cy = coords[n*3+1], cz = coords[n*3+2];
    float base = values[n] + bd[n];
    float wd[8];
    #pragma unroll
    for (int l = 0; l < 8; l++) wd[l] = Wd[(size_t)l * N + n];

    #pragma unroll
    for (int b = 0; b < BB; b++) {
        const float* p = &sp[b * 16];
        // ascending-K fma chain: fma(r2,c2, fma(r1,c1, r0*c0))
        float xr = __fmaf_rn(p[2], cz, __fmaf_rn(p[1], cy, __fmul_rn(p[0], cx)));
        float yr = __fmaf_rn(p[5], cz, __fmaf_rn(p[4], cy, __fmul_rn(p[3], cx)));
        float fx = rintf(__fadd_rn(__fadd_rn(xr, p[6]), 128.0f));
        float fy = rintf(__fadd_rn(__fadd_rn(yr, p[7]), 128.0f));
        fx = fminf(fmaxf(fx, 0.f), 255.f);
        fy = fminf(fmaxf(fy, 0.f), 255.f);
        int ix = (int)fx, iy = (int)fy;
        float val = base;
        #pragma unroll
        for (int l = 0; l < 8; l++) val = fmaf(p[8+l], wd[l], val);
        atomicAdd(&g_img[(b << 16) + (iy << 8) + ix], val);
    }
}

// ---------------- separable gaussian blur (zero-padded SAME) ----------------
__global__ void blur_y_kernel() {   // g_img -> g_tmp, along rows (y)
    int idx = blockIdx.x * blockDim.x + threadIdx.x;
    if (idx >= NPIX) return;
    int x = idx & 255, y = (idx >> 8) & 255, b = idx >> 16;
    float acc = 0.f;
    #pragma unroll
    for (int d = -3; d <= 3; d++) {
        int yy = y + d;
        if (yy >= 0 && yy < 256)
            acc = fmaf(g_gauss[d+3], g_img[(b << 16) + (yy << 8) + x], acc);
    }
    g_tmp[idx] = acc;
}
__global__ void blur_x_kernel() {   // g_tmp -> g_img, along cols (x)
    int idx = blockIdx.x * blockDim.x + threadIdx.x;
    if (idx >= NPIX) return;
    int x = idx & 255;
    float acc = 0.f;
    #pragma unroll
    for (int d = -3; d <= 3; d++) {
        int xx = x + d;
        if (xx >= 0 && xx < 256)
            acc = fmaf(g_gauss[d+3], g_tmp[idx - x + xx], acc);
    }
    g_img[idx] = acc;
}

// ---------------- radix-2 Stockham 256-pt FFT (128 threads) ----------------
// DIF Stockham, natural-order output. Result ends in buf0.
// sgn = -1 forward, +1 inverse (unnormalized).
__device__ __forceinline__ void fft256(float2* a, float2* b, const float2* tw,
                                       int t, float sgn) {
    int m = 1;
    #pragma unroll
    for (int s = 0; s < 8; s++) {
        int jm = t & ~(m - 1);
        float2 c0 = a[t], c1 = a[t + 128];
        float dx = c0.x - c1.x, dy = c0.y - c1.y;
        float2 w = tw[jm];
        float wy = sgn * w.y;
        b[t + jm]     = make_float2(c0.x + c1.x, c0.y + c1.y);
        b[t + jm + m] = make_float2(w.x*dx - wy*dy, w.x*dy + wy*dx);
        __syncthreads();
        float2* tp = a; a = b; b = tp;
        m <<= 1;
    }
}

__device__ __forceinline__ void fill_tw(float2* tw, int t) {
    float s, c;
    sincospif((float)t / 128.0f, &s, &c);   // angle = 2*pi*t/256
    tw[t] = make_float2(c, s);              // sgn applied at use site
}

// Stage A: forward rfft along rows. One block per (b,y).
__global__ void fft_row_fwd_kernel() {
    __shared__ float2 buf0[256], buf1[256], tw[128];
    int t = threadIdx.x;
    int bid = blockIdx.x;                    // b*256 + y
    const float* row = &g_img[bid * 256];
    buf0[t]       = make_float2(row[t], 0.f);
    buf0[t + 128] = make_float2(row[t + 128], 0.f);
    fill_tw(tw, t);
    __syncthreads();
    fft256(buf0, buf1, tw, t, -1.0f);
    float2* out = &g_A[(size_t)bid * HALFK];
    out[t] = buf0[t];
    if (t == 0) out[128] = buf0[128];
}

// Stage B+C fused: column forward fft, CTF multiply, column inverse fft.
// One block per (b, kx).
__global__ void fft_col_ctf_kernel(const float* __restrict__ ctf) {
    __shared__ float2 buf0[256], buf1[256], tw[128];
    int t = threadIdx.x;
    int b  = blockIdx.x / HALFK;
    int kx = blockIdx.x % HALFK;
    size_t base = (size_t)(b * 256) * HALFK + kx;
    buf0[t]       = g_A[base + (size_t)t * HALFK];
    buf0[t + 128] = g_A[base + (size_t)(t + 128) * HALFK];
    fill_tw(tw, t);
    __syncthreads();
    fft256(buf0, buf1, tw, t, -1.0f);
    // multiply by ctf[b, ky, kx]
    float f0 = ctf[(size_t)(b * 256 + t)       * HALFK + kx];
    float f1 = ctf[(size_t)(b * 256 + t + 128) * HALFK + kx];
    buf0[t].x       *= f0;  buf0[t].y       *= f0;
    buf0[t + 128].x *= f1;  buf0[t + 128].y *= f1;
    __syncthreads();
    fft256(buf0, buf1, tw, t, +1.0f);
    g_A[base + (size_t)t * HALFK]         = buf0[t];
    g_A[base + (size_t)(t + 128) * HALFK] = buf0[t + 128];
}

// Stage D: inverse rfft along rows (Hermitian extension + full inverse, take Re).
__global__ void fft_row_inv_kernel(float* __restrict__ out) {
    __shared__ float2 buf0[256], buf1[256], tw[128];
    int t = threadIdx.x;
    int bid = blockIdx.x;                    // b*256 + y
    const float2* A = &g_A[(size_t)bid * HALFK];
    float2 v = A[t];
    buf0[t] = v;
    if (t == 0) buf0[128] = A[128];
    else        buf0[256 - t] = make_float2(v.x, -v.y);
    fill_tw(tw, t);
    __syncthreads();
    fft256(buf0, buf1, tw, t, +1.0f);
    const float scale = 1.0f / 65536.0f;     // 1/(256*256)
    out[bid * 256 + t]       = buf0[t].x       * scale;
    out[bid * 256 + t + 128] = buf0[t + 128].x * scale;
}

// ---------------- launch ----------------
extern "C" void kernel_launch(void* const* d_in, const int* in_sizes, int n_in,
                              void* d_out, int out_size) {
    const float* rows   = (const float*)d_in[0];
    const float* shifts = (const float*)d_in[1];
    const float* latent = (const float*)d_in[2];
    const float* coords = (const float*)d_in[3];
    const float* values = (const float*)d_in[4];
    const float* W0 = (const float*)d_in[5];
    const float* b0 = (const float*)d_in[6];
    const float* W1 = (const float*)d_in[7];
    const float* b1 = (const float*)d_in[8];
    const float* W2 = (const float*)d_in[9];
    const float* b2 = (const float*)d_in[10];
    const float* W3 = (const float*)d_in[11];
    const float* b3 = (const float*)d_in[12];
    const float* Wd = (const float*)d_in[13];
    const float* bd = (const float*)d_in[14];
    const float* ctf = (const float*)d_in[15];
    int N = in_sizes[4];

    zero_kernel<<<(NPIX / 4 + 255) / 256, 256>>>();
    prep_kernel<<<1, 32>>>(rows, shifts, latent, W0, b0, W1, b1, W2, b2, W3, b3);
    scatter_kernel<<<(N + 255) / 256, 256>>>(coords, values, Wd, bd, N);
    blur_y_kernel<<<NPIX / 256, 256>>>();
    blur_x_kernel<<<NPIX / 256, 256>>>();
    fft_row_fwd_kernel<<<BB * XS, 128>>>();
    fft_col_ctf_kernel<<<BB * HALFK, 128>>>(ctf);
    fft_row_inv_kernel<<<BB * XS, 128>>>((float*)d_out);
}

// round 4
// speedup vs baseline: 1.1656x; 1.1656x over previous
#include <cuda_runtime.h>
#include <math.h>

#define XS   256
#define BB   16
#define HALFK 129               // XS/2 + 1
#define NPIX (BB * XS * XS)

// ---------------- scratch (device globals: no allocation allowed) ----------
__device__ float  g_prep[BB * 16];      // per batch: R00..R12 (6), s0, s1, h[8]
__device__ float  g_gauss[7];
__device__ float  g_img[NPIX];          // scatter target
__device__ float2 g_A[BB * XS * HALFK]; // half-spectrum [b][y/ky][kx]

// ---------------- zero image ----------------
__global__ void zero_kernel() {
    int i = blockIdx.x * blockDim.x + threadIdx.x;
    float4* p = (float4*)g_img;
    if (i < NPIX / 4) p[i] = make_float4(0.f, 0.f, 0.f, 0.f);
}

// ---------------- prep: rotations + SIREN head + gaussian taps -------------
__global__ void prep_kernel(const float* __restrict__ rows,
                            const float* __restrict__ shifts,
                            const float* __restrict__ latent,
                            const float* __restrict__ W0, const float* __restrict__ b0,
                            const float* __restrict__ W1, const float* __restrict__ b1,
                            const float* __restrict__ W2, const float* __restrict__ b2,
                            const float* __restrict__ W3, const float* __restrict__ b3) {
    int b = threadIdx.x;
    if (b < BB) {
        float rot = rows[b*3+0], tilt = rows[b*3+1], psi = rows[b*3+2];
        float ca = cosf(rot),  sa = sinf(rot);
        float cb = cosf(tilt), sb = sinf(tilt);
        float cg = cosf(psi),  sg = sinf(psi);
        float nsg = -sg;
        float* p = &g_prep[b * 16];
        p[0] = __fsub_rn(__fmul_rn(__fmul_rn(cg, cb), ca), __fmul_rn(sg, sa));
        p[1] = __fadd_rn(__fmul_rn(__fmul_rn(cg, cb), sa), __fmul_rn(sg, ca));
        p[2] = -__fmul_rn(cg, sb);
        p[3] = __fsub_rn(__fmul_rn(__fmul_rn(nsg, cb), ca), __fmul_rn(cg, sa));
        p[4] = __fadd_rn(__fmul_rn(__fmul_rn(nsg, cb), sa), __fmul_rn(cg, ca));
        p[5] = __fmul_rn(sg, sb);
        p[6] = shifts[b*2+0];
        p[7] = shifts[b*2+1];

        float h[8];
        #pragma unroll
        for (int j = 0; j < 8; j++) {
            float acc = b0[j];
            #pragma unroll
            for (int l = 0; l < 8; l++) acc += latent[b*8+l] * W0[l*8+j];
            h[j] = sinf(30.0f * acc);
        }
        const float* Ws[3] = {W1, W2, W3};
        const float* bs[3] = {b1, b2, b3};
        for (int s = 0; s < 3; s++) {
            float t[8];
            #pragma unroll
            for (int j = 0; j < 8; j++) {
                float acc = bs[s][j];
                #pragma unroll
                for (int l = 0; l < 8; l++) acc += h[l] * Ws[s][l*8+j];
                t[j] = sinf(acc);
            }
            #pragma unroll
            for (int j = 0; j < 8; j++) h[j] += t[j];
        }
        #pragma unroll
        for (int j = 0; j < 8; j++) p[8+j] = h[j];
    }
    if (threadIdx.x == 0) {
        float k[7], s = 0.f;
        for (int i = 0; i < 7; i++) { float x = (float)(i - 3); k[i] = expf(-0.5f * x * x); s += k[i]; }
        for (int i = 0; i < 7; i++) g_gauss[i] = k[i] / s;
    }
}

// ---------------- scatter (arithmetic bit-identical to R2 pass) -------------
__global__ void scatter_kernel(const float* __restrict__ coords,
                               const float* __restrict__ values,
                               const float* __restrict__ Wd,
                               const float* __restrict__ bd,
                               int N) {
    __shared__ float sp[256];  // 16 batches x 16 floats
    if (threadIdx.x < 256) sp[threadIdx.x] = g_prep[threadIdx.x];
    __syncthreads();

    int n = blockIdx.x * blockDim.x + threadIdx.x;
    if (n >= N) return;

    float cx = coords[n*3+0], cy = coords[n*3+1], cz = coords[n*3+2];
    float base = values[n] + bd[n];
    float wd[8];
    #pragma unroll
    for (int l = 0; l < 8; l++) wd[l] = Wd[(size_t)l * N + n];

    #pragma unroll
    for (int b = 0; b < BB; b++) {
        const float* p = &sp[b * 16];
        float xr = __fmaf_rn(p[2], cz, __fmaf_rn(p[1], cy, __fmul_rn(p[0], cx)));
        float yr = __fmaf_rn(p[5], cz, __fmaf_rn(p[4], cy, __fmul_rn(p[3], cx)));
        float fx = rintf(__fadd_rn(__fadd_rn(xr, p[6]), 128.0f));
        float fy = rintf(__fadd_rn(__fadd_rn(yr, p[7]), 128.0f));
        fx = fminf(fmaxf(fx, 0.f), 255.f);
        fy = fminf(fmaxf(fy, 0.f), 255.f);
        int ix = (int)fx, iy = (int)fy;
        float val = base;
        #pragma unroll
        for (int l = 0; l < 8; l++) val = fmaf(p[8+l], wd[l], val);
        atomicAdd(&g_img[(b << 16) + (iy << 8) + ix], val);
    }
}

// ---------------- radix-2 Stockham 256-pt FFT (128 butterfly threads) -------
// Result ends in the buffer passed as 'a'. sgn=-1 fwd, +1 inv (unnormalized).
__device__ __forceinline__ void fft256(float2* a, float2* b, const float2* tw,
                                       int t, float sgn) {
    int m = 1;
    #pragma unroll
    for (int s = 0; s < 8; s++) {
        int jm = t & ~(m - 1);
        float2 c0 = a[t], c1 = a[t + 128];
        float dx = c0.x - c1.x, dy = c0.y - c1.y;
        float2 w = tw[jm];
        float wy = sgn * w.y;
        b[t + jm]     = make_float2(c0.x + c1.x, c0.y + c1.y);
        b[t + jm + m] = make_float2(w.x*dx - wy*dy, w.x*dy + wy*dx);
        __syncthreads();
        float2* tp = a; a = b; b = tp;
        m <<= 1;
    }
}

__device__ __forceinline__ void fill_tw(float2* tw, int t) {
    float s, c;
    sincospif((float)t / 128.0f, &s, &c);   // angle = 2*pi*t/256
    tw[t] = make_float2(c, s);
}

// Stage A: x-blur + forward rfft of TWO rows packed into one complex FFT.
// One block per (b, row-pair).
__global__ void fftA_kernel() {
    __shared__ float2 buf0[256], buf1[256], tw[128];
    float* raw = (float*)buf1;               // 512 floats: two raw rows
    int t  = threadIdx.x;
    int b  = blockIdx.x >> 7;
    int y0 = (blockIdx.x & 127) * 2;
    const float* r0 = &g_img[(b * 256 + y0) * 256];
    raw[t]           = r0[t];
    raw[t + 128]     = r0[t + 128];
    raw[256 + t]     = r0[256 + t];
    raw[256 + t + 128] = r0[256 + t + 128];
    float w[7];
    #pragma unroll
    for (int i = 0; i < 7; i++) w[i] = g_gauss[i];
    fill_tw(tw, t);
    __syncthreads();

    float2 z0, z1;
    #pragma unroll
    for (int half = 0; half < 2; half++) {
        int x = t + half * 128;
        float a0 = 0.f, a1 = 0.f;
        #pragma unroll
        for (int d = -3; d <= 3; d++) {
            int xx = x + d;
            if (xx >= 0 && xx < 256) {
                a0 = fmaf(w[d+3], raw[xx], a0);
                a1 = fmaf(w[d+3], raw[256 + xx], a1);
            }
        }
        if (half == 0) z0 = make_float2(a0, a1);
        else           z1 = make_float2(a0, a1);
    }
    __syncthreads();            // all raw reads done before FFT overwrites buf1
    buf0[t]       = z0;
    buf0[t + 128] = z1;
    __syncthreads();
    fft256(buf0, buf1, tw, t, -1.0f);

    // Unpack packed real FFT: A1 = (Z + conj(Zr))/2 ; A2 = -i(Z - conj(Zr))/2
    float2 Z1 = buf0[t];
    float2 Z2 = buf0[(256 - t) & 255];
    float2 A1 = make_float2(0.5f*(Z1.x + Z2.x), 0.5f*(Z1.y - Z2.y));
    float2 A2 = make_float2(0.5f*(Z1.y + Z2.y), 0.5f*(Z2.x - Z1.x));
    float2* o1 = &g_A[(size_t)(b * 256 + y0) * HALFK];
    float2* o2 = o1 + HALFK;
    o1[t] = A1;
    o2[t] = A2;
    if (t == 0) {
        float2 Zn = buf0[128];
        o1[128] = make_float2(Zn.x, 0.f);
        o2[128] = make_float2(Zn.y, 0.f);
    }
}

// Stage B: y-blur + column fwd FFT + CTF + column inv FFT.
// 4 kx columns per 512-thread block. raw aliases buf1.
__global__ void fftB_kernel(const float* __restrict__ ctf) {
    __shared__ float2 buf0[1024], buf1[1024], tw[128];
    float2* raw = buf1;
    int tid = threadIdx.x;
    int c = tid >> 7, t = tid & 127;
    int b   = blockIdx.x / 33;
    int kx0 = (blockIdx.x % 33) * 4;

    #pragma unroll
    for (int r = 0; r < 2; r++) {
        int e  = tid + r * 512;
        int cc = e & 3, ky = e >> 2;
        int kx = min(kx0 + cc, 128);
        raw[cc * 256 + ky] = g_A[(size_t)(b * 256 + ky) * HALFK + kx];
    }
    float w[7];
    #pragma unroll
    for (int i = 0; i < 7; i++) w[i] = g_gauss[i];
    fill_tw(tw, t);
    __syncthreads();

    // y-blur (zero-padded) on this column; row index here is spatial y
    float2 z0 = make_float2(0.f, 0.f), z1 = make_float2(0.f, 0.f);
    #pragma unroll
    for (int d = -3; d <= 3; d++) {
        int ya = t + d;
        if (ya >= 0 && ya < 256) {
            float2 v = raw[c * 256 + ya];
            z0.x = fmaf(w[d+3], v.x, z0.x); z0.y = fmaf(w[d+3], v.y, z0.y);
        }
        int yb = t + 128 + d;
        if (yb >= 0 && yb < 256) {
            float2 v = raw[c * 256 + yb];
            z1.x = fmaf(w[d+3], v.x, z1.x); z1.y = fmaf(w[d+3], v.y, z1.y);
        }
    }
    __syncthreads();            // raw reads complete before FFT writes buf1
    buf0[c * 256 + t]       = z0;
    buf0[c * 256 + t + 128] = z1;
    __syncthreads();
    fft256(buf0 + c * 256, buf1 + c * 256, tw, t, -1.0f);

    int kxc = min(kx0 + c, 128);
    float f0 = ctf[(size_t)(b * 256 + t)       * HALFK + kxc];
    float f1 = ctf[(size_t)(b * 256 + t + 128) * HALFK + kxc];
    float2 u0 = buf0[c * 256 + t], u1 = buf0[c * 256 + t + 128];
    u0.x *= f0; u0.y *= f0; u1.x *= f1; u1.y *= f1;
    buf0[c * 256 + t]       = u0;
    buf0[c * 256 + t + 128] = u1;
    __syncthreads();
    fft256(buf0 + c * 256, buf1 + c * 256, tw, t, 1.0f);

    #pragma unroll
    for (int r = 0; r < 2; r++) {
        int e  = tid + r * 512;
        int cc = e & 3, ky = e >> 2;
        int kx = kx0 + cc;
        if (kx <= 128)
            g_A[(size_t)(b * 256 + ky) * HALFK + kx] = buf0[cc * 256 + ky];
    }
}

// Stage D: inverse rfft of TWO rows at once (S1 + i*S2 trick).
// CRITICAL: the pack requires exactly-Hermitian extensions, so the imaginary
// parts of the DC (kx=0) and Nyquist (kx=128) bins MUST be dropped (irfft
// semantics ignore them; keeping them cross-contaminates the two rows).
__global__ void fftD_kernel(float* __restrict__ out) {
    __shared__ float2 buf0[256], buf1[256], tw[128];
    int t  = threadIdx.x;
    int b  = blockIdx.x >> 7;
    int y0 = (blockIdx.x & 127) * 2;
    const float2* A1 = &g_A[(size_t)(b * 256 + y0) * HALFK];
    const float2* A2 = A1 + HALFK;

    if (t == 0) {
        float2 a1 = A1[0],  a2 = A2[0];
        float2 n1 = A1[128], n2 = A2[128];
        buf0[0]   = make_float2(a1.x, a2.x);   // Im(DC) dropped
        buf0[128] = make_float2(n1.x, n2.x);   // Im(Nyquist) dropped
    } else {
        float2 a1 = A1[t], a2 = A2[t];
        buf0[t] = make_float2(a1.x - a2.y, a1.y + a2.x);       // Z[t] = S1 + i*S2
        float2 m1 = A1[128 - t], m2 = A2[128 - t];             // Z[t+128] from conj
        buf0[t + 128] = make_float2(m1.x + m2.y, m2.x - m1.y);
    }
    fill_tw(tw, t);
    __syncthreads();
    fft256(buf0, buf1, tw, t, 1.0f);

    const float s = 1.0f / 65536.0f;   // 1/(256*256): both inverse dims
    float* o0 = &out[(size_t)(b * 256 + y0) * 256];
    float* o1 = o0 + 256;
    float2 v0 = buf0[t], v1 = buf0[t + 128];
    o0[t]       = v0.x * s;  o1[t]       = v0.y * s;
    o0[t + 128] = v1.x * s;  o1[t + 128] = v1.y * s;
}

// ---------------- launch ----------------
extern "C" void kernel_launch(void* const* d_in, const int* in_sizes, int n_in,
                              void* d_out, int out_size) {
    const float* rows   = (const float*)d_in[0];
    const float* shifts = (const float*)d_in[1];
    const float* latent = (const float*)d_in[2];
    const float* coords = (const float*)d_in[3];
    const float* values = (const float*)d_in[4];
    const float* W0 = (const float*)d_in[5];
    const float* b0 = (const float*)d_in[6];
    const float* W1 = (const float*)d_in[7];
    const float* b1 = (const float*)d_in[8];
    const float* W2 = (const float*)d_in[9];
    const float* b2 = (const float*)d_in[10];
    const float* W3 = (const float*)d_in[11];
    const float* b3 = (const float*)d_in[12];
    const float* Wd = (const float*)d_in[13];
    const float* bd = (const float*)d_in[14];
    const float* ctf = (const float*)d_in[15];
    int N = in_sizes[4];

    zero_kernel<<<(NPIX / 4 + 255) / 256, 256>>>();
    prep_kernel<<<1, 32>>>(rows, shifts, latent, W0, b0, W1, b1, W2, b2, W3, b3);
    scatter_kernel<<<(N + 255) / 256, 256>>>(coords, values, Wd, bd, N);
    fftA_kernel<<<BB * 128, 128>>>();
    fftB_kernel<<<BB * 33, 512>>>(ctf);
    fftD_kernel<<<BB * 128, 128>>>((float*)d_out);
}

// round 5
// speedup vs baseline: 1.1939x; 1.0243x over previous
#include <cuda_runtime.h>
#include <math.h>

#define XS   256
#define BB   16
#define HALFK 129               // XS/2 + 1
#define NPIX (BB * XS * XS)
#define SK(i) ((i) + ((i) >> 5))   // smem bank skew

// ---------------- scratch (device globals: no allocation allowed) ----------
__device__ float  g_prep[BB * 16];      // per batch: R00..R12 (6), s0, s1, h[8]
__device__ float  g_gauss[7];
__device__ float  g_img[NPIX];          // scatter target
__device__ float2 g_A[BB * XS * HALFK]; // half-spectrum [b][y/ky][kx]

// ---------------- fused zero + prep ----------------
__global__ void zero_prep_kernel(const float* __restrict__ rows,
                                 const float* __restrict__ shifts,
                                 const float* __restrict__ latent,
                                 const float* __restrict__ W0, const float* __restrict__ b0,
                                 const float* __restrict__ W1, const float* __restrict__ b1,
                                 const float* __restrict__ W2, const float* __restrict__ b2,
                                 const float* __restrict__ W3, const float* __restrict__ b3) {
    if (blockIdx.x == 0) {
        int b = threadIdx.x;
        if (b < BB) {
            float rot = rows[b*3+0], tilt = rows[b*3+1], psi = rows[b*3+2];
            float ca = cosf(rot),  sa = sinf(rot);
            float cb = cosf(tilt), sb = sinf(tilt);
            float cg = cosf(psi),  sg = sinf(psi);
            float nsg = -sg;
            float* p = &g_prep[b * 16];
            p[0] = __fsub_rn(__fmul_rn(__fmul_rn(cg, cb), ca), __fmul_rn(sg, sa));
            p[1] = __fadd_rn(__fmul_rn(__fmul_rn(cg, cb), sa), __fmul_rn(sg, ca));
            p[2] = -__fmul_rn(cg, sb);
            p[3] = __fsub_rn(__fmul_rn(__fmul_rn(nsg, cb), ca), __fmul_rn(cg, sa));
            p[4] = __fadd_rn(__fmul_rn(__fmul_rn(nsg, cb), sa), __fmul_rn(cg, ca));
            p[5] = __fmul_rn(sg, sb);
            p[6] = shifts[b*2+0];
            p[7] = shifts[b*2+1];

            float h[8];
            #pragma unroll
            for (int j = 0; j < 8; j++) {
                float acc = b0[j];
                #pragma unroll
                for (int l = 0; l < 8; l++) acc += latent[b*8+l] * W0[l*8+j];
                h[j] = sinf(30.0f * acc);
            }
            const float* Ws[3] = {W1, W2, W3};
            const float* bs[3] = {b1, b2, b3};
            for (int s = 0; s < 3; s++) {
                float t[8];
                #pragma unroll
                for (int j = 0; j < 8; j++) {
                    float acc = bs[s][j];
                    #pragma unroll
                    for (int l = 0; l < 8; l++) acc += h[l] * Ws[s][l*8+j];
                    t[j] = sinf(acc);
                }
                #pragma unroll
                for (int j = 0; j < 8; j++) h[j] += t[j];
            }
            #pragma unroll
            for (int j = 0; j < 8; j++) p[8+j] = h[j];
        }
        if (threadIdx.x == 0) {
            float k[7], s = 0.f;
            for (int i = 0; i < 7; i++) { float x = (float)(i - 3); k[i] = expf(-0.5f * x * x); s += k[i]; }
            for (int i = 0; i < 7; i++) g_gauss[i] = k[i] / s;
        }
    }
    int i = blockIdx.x * blockDim.x + threadIdx.x;
    float4* p4 = (float4*)g_img;
    if (i < NPIX / 4) p4[i] = make_float4(0.f, 0.f, 0.f, 0.f);
}

// ---------------- scatter (arithmetic bit-identical to R2/R4 pass) ----------
__global__ void scatter_kernel(const float* __restrict__ coords,
                               const float* __restrict__ values,
                               const float* __restrict__ Wd,
                               const float* __restrict__ bd,
                               int N) {
    __shared__ float sp[256];  // 16 batches x 16 floats
    if (threadIdx.x < 256) sp[threadIdx.x] = g_prep[threadIdx.x];
    __syncthreads();

    int n = blockIdx.x * blockDim.x + threadIdx.x;
    if (n >= N) return;

    float cx = coords[n*3+0], cy = coords[n*3+1], cz = coords[n*3+2];
    float base = values[n] + bd[n];
    float wd[8];
    #pragma unroll
    for (int l = 0; l < 8; l++) wd[l] = Wd[(size_t)l * N + n];

    #pragma unroll
    for (int b = 0; b < BB; b++) {
        const float* p = &sp[b * 16];
        float xr = __fmaf_rn(p[2], cz, __fmaf_rn(p[1], cy, __fmul_rn(p[0], cx)));
        float yr = __fmaf_rn(p[5], cz, __fmaf_rn(p[4], cy, __fmul_rn(p[3], cx)));
        float fx = rintf(__fadd_rn(__fadd_rn(xr, p[6]), 128.0f));
        float fy = rintf(__fadd_rn(__fadd_rn(yr, p[7]), 128.0f));
        fx = fminf(fmaxf(fx, 0.f), 255.f);
        fy = fminf(fmaxf(fy, 0.f), 255.f);
        int ix = (int)fx, iy = (int)fy;
        float val = base;
        #pragma unroll
        for (int l = 0; l < 8; l++) val = fmaf(p[8+l], wd[l], val);
        atomicAdd(&g_img[(b << 16) + (iy << 8) + ix], val);
    }
}

// ---------------- radix-4 Stockham 256-pt FFT (64 threads / transform) -----
// Exact fusion of two radix-2 Stockham stages -> identical natural ordering.
// tw[k] = e^{+2pi i k/256}, k in [0,192). sgn=-1 fwd, +1 inv (unnormalized).
// Data slice at offset o in b0/b1 (skewed addressing). Result ends in b0.
__device__ __forceinline__ float2 cmul_sgn(float2 w, float2 v, float sgn) {
    float wy = sgn * w.y;
    return make_float2(fmaf(w.x, v.x, -wy * v.y), fmaf(w.x, v.y, wy * v.x));
}

__device__ __forceinline__ void fft256_r4(float2* b0, float2* b1, const float2* tw,
                                          int o, int t, float sgn) {
    float2 *a = b0, *b = b1;
    #pragma unroll
    for (int m = 1; m < 256; m <<= 2) {
        int k = t & ~(m - 1);
        float2 c0 = a[SK(o + t)],       c1 = a[SK(o + t + 64)];
        float2 c2 = a[SK(o + t + 128)], c3 = a[SK(o + t + 192)];
        float2 t0 = make_float2(c0.x + c2.x, c0.y + c2.y);
        float2 t1 = make_float2(c0.x - c2.x, c0.y - c2.y);
        float2 t2 = make_float2(c1.x + c3.x, c1.y + c3.y);
        float2 t3 = make_float2(c1.x - c3.x, c1.y - c3.y);
        float2 u3 = make_float2(-sgn * t3.y, sgn * t3.x);   // (-+i)*t3
        float2 e0 = make_float2(t0.x + t2.x, t0.y + t2.y);
        float2 d1 = make_float2(t0.x - t2.x, t0.y - t2.y);
        float2 d2 = make_float2(t1.x + u3.x, t1.y + u3.y);
        float2 d3 = make_float2(t1.x - u3.x, t1.y - u3.y);
        int B = o + 3 * k + t;                              // o + 4k + (t-k)
        b[SK(B)]         = e0;
        b[SK(B + m)]     = cmul_sgn(tw[k],     d2, sgn);
        b[SK(B + 2*m)]   = cmul_sgn(tw[2 * k], d1, sgn);
        b[SK(B + 3*m)]   = cmul_sgn(tw[3 * k], d3, sgn);
        __syncthreads();
        float2* tp = a; a = b; b = tp;
    }
}

__device__ __forceinline__ void fill_tw(float2* tw, int tid, int nthreads) {
    for (int i = tid; i < 192; i += nthreads) {
        float s, c;
        sincospif((float)i / 128.0f, &s, &c);
        tw[i] = make_float2(c, s);
    }
}

// Stage A: x-blur + forward rfft of TWO rows packed per transform.
// 256-thread block = 4 transforms = 8 rows.
__global__ void fftA_kernel() {
    __shared__ float2 buf0[1056], buf1[1056], tw[192];
    float* raw = (float*)buf1;               // 2048 floats = 8 raw rows
    int tid = threadIdx.x;
    int c = tid >> 6, t = tid & 63;
    int b  = blockIdx.x >> 5;
    int y0 = (blockIdx.x & 31) * 8;
    const float* src = &g_img[(b * 256 + y0) * 256];
    #pragma unroll
    for (int j = 0; j < 8; j++) raw[tid + j * 256] = src[tid + j * 256];
    fill_tw(tw, tid, 256);
    float w[7];
    #pragma unroll
    for (int i = 0; i < 7; i++) w[i] = g_gauss[i];
    __syncthreads();

    // blur rows 2c, 2c+1 at x = t + 64j
    float2 zz[4];
    #pragma unroll
    for (int j = 0; j < 4; j++) {
        int x = t + 64 * j;
        float a0 = 0.f, a1 = 0.f;
        #pragma unroll
        for (int d = -3; d <= 3; d++) {
            int xx = x + d;
            if (xx >= 0 && xx < 256) {
                a0 = fmaf(w[d+3], raw[(2*c)   * 256 + xx], a0);
                a1 = fmaf(w[d+3], raw[(2*c+1) * 256 + xx], a1);
            }
        }
        zz[j] = make_float2(a0, a1);
    }
    __syncthreads();            // raw reads done before FFT overwrites buf1
    #pragma unroll
    for (int j = 0; j < 4; j++) buf0[SK(c * 256 + t + 64 * j)] = zz[j];
    __syncthreads();
    fft256_r4(buf0, buf1, tw, c * 256, t, -1.0f);

    // Unpack packed real FFT: A1 = (Z + conj(Zr))/2 ; A2 = -i(Z - conj(Zr))/2
    float2* o1 = &g_A[(size_t)(b * 256 + y0 + 2 * c) * HALFK];
    float2* o2 = o1 + HALFK;
    #pragma unroll
    for (int j = 0; j < 2; j++) {
        int kx = t + 64 * j;
        float2 Z1 = buf0[SK(c * 256 + kx)];
        float2 Z2 = buf0[SK(c * 256 + ((256 - kx) & 255))];
        o1[kx] = make_float2(0.5f*(Z1.x + Z2.x), 0.5f*(Z1.y - Z2.y));
        o2[kx] = make_float2(0.5f*(Z1.y + Z2.y), 0.5f*(Z2.x - Z1.x));
    }
    if (t == 0) {
        float2 Zn = buf0[SK(c * 256 + 128)];
        o1[128] = make_float2(Zn.x, 0.f);
        o2[128] = make_float2(Zn.y, 0.f);
    }
}

// Stage B: y-blur + column fwd FFT + CTF + column inv FFT.
// 256-thread block = 4 kx columns (64-thread transforms). raw aliases buf1.
__global__ void fftB_kernel(const float* __restrict__ ctf) {
    __shared__ float2 buf0[1056], buf1[1056], tw[192];
    float2* raw = buf1;
    int tid = threadIdx.x;
    int c = tid >> 6, t = tid & 63;
    int b   = blockIdx.x / 33;
    int kx0 = (blockIdx.x % 33) * 4;

    #pragma unroll
    for (int r = 0; r < 4; r++) {
        int e  = tid + r * 256;
        int cc = e & 3, ky = e >> 2;
        int kx = min(kx0 + cc, 128);
        raw[cc * 256 + ky] = g_A[(size_t)(b * 256 + ky) * HALFK + kx];
    }
    fill_tw(tw, tid, 256);
    float w[7];
    #pragma unroll
    for (int i = 0; i < 7; i++) w[i] = g_gauss[i];
    __syncthreads();

    // y-blur (zero-padded); row index here is spatial y
    float2 zz[4];
    #pragma unroll
    for (int j = 0; j < 4; j++) {
        int y = t + 64 * j;
        float2 acc = make_float2(0.f, 0.f);
        #pragma unroll
        for (int d = -3; d <= 3; d++) {
            int yy = y + d;
            if (yy >= 0 && yy < 256) {
                float2 v = raw[c * 256 + yy];
                acc.x = fmaf(w[d+3], v.x, acc.x);
                acc.y = fmaf(w[d+3], v.y, acc.y);
            }
        }
        zz[j] = acc;
    }
    __syncthreads();            // raw reads complete before FFT writes buf1
    #pragma unroll
    for (int j = 0; j < 4; j++) buf0[SK(c * 256 + t + 64 * j)] = zz[j];
    __syncthreads();
    fft256_r4(buf0, buf1, tw, c * 256, t, -1.0f);

    int kxc = min(kx0 + c, 128);
    #pragma unroll
    for (int j = 0; j < 4; j++) {
        int ky = t + 64 * j;
        float f = ctf[(size_t)(b * 256 + ky) * HALFK + kxc];
        float2 v = buf0[SK(c * 256 + ky)];
        buf0[SK(c * 256 + ky)] = make_float2(v.x * f, v.y * f);
    }
    // no barrier needed: radix-4 stage 1 reads exactly this thread's elements
    fft256_r4(buf0, buf1, tw, c * 256, t, 1.0f);

    #pragma unroll
    for (int r = 0; r < 4; r++) {
        int e  = tid + r * 256;
        int cc = e & 3, ky = e >> 2;
        int kx = kx0 + cc;
        if (kx <= 128)
            g_A[(size_t)(b * 256 + ky) * HALFK + kx] = buf0[SK(cc * 256 + ky)];
    }
}

// Stage D: inverse rfft of TWO rows per transform (S1 + i*S2 pack).
// Im of DC/Nyquist dropped (irfft semantics; keeps pack exactly Hermitian).
__global__ void fftD_kernel(float* __restrict__ out) {
    __shared__ float2 buf0[1056], buf1[1056], tw[192];
    int tid = threadIdx.x;
    int c = tid >> 6, t = tid & 63;
    int b  = blockIdx.x >> 5;
    int y0 = (blockIdx.x & 31) * 8 + 2 * c;
    const float2* A1 = &g_A[(size_t)(b * 256 + y0) * HALFK];
    const float2* A2 = A1 + HALFK;
    int o = c * 256;

    if (t == 0) {
        buf0[SK(o + 0)]   = make_float2(A1[0].x,   A2[0].x);    // Im(DC) dropped
        buf0[SK(o + 128)] = make_float2(A1[128].x, A2[128].x);  // Im(Nyq) dropped
    } else {
        float2 a1 = A1[t], a2 = A2[t];
        buf0[SK(o + t)] = make_float2(a1.x - a2.y, a1.y + a2.x);
        int m = 128 - t;                                        // j = t+128
        float2 m1 = A1[m], m2 = A2[m];
        buf0[SK(o + t + 128)] = make_float2(m1.x + m2.y, m2.x - m1.y);
    }
    {
        int j = t + 64;                                         // [64,128)
        float2 a1 = A1[j], a2 = A2[j];
        buf0[SK(o + j)] = make_float2(a1.x - a2.y, a1.y + a2.x);
    }
    {
        int m = 64 - t;                                         // j = t+192
        float2 m1 = A1[m], m2 = A2[m];
        buf0[SK(o + t + 192)] = make_float2(m1.x + m2.y, m2.x - m1.y);
    }
    fill_tw(tw, tid, 256);
    __syncthreads();
    fft256_r4(buf0, buf1, tw, o, t, 1.0f);

    const float s = 1.0f / 65536.0f;   // 1/(256*256)
    float* o0 = &out[(size_t)(b * 256 + y0) * 256];
    float* o1 = o0 + 256;
    #pragma unroll
    for (int j = 0; j < 4; j++) {
        float2 v = buf0[SK(o + t + 64 * j)];
        o0[t + 64 * j] = v.x * s;
        o1[t + 64 * j] = v.y * s;
    }
}

// ---------------- launch ----------------
extern "C" void kernel_launch(void* const* d_in, const int* in_sizes, int n_in,
                              void* d_out, int out_size) {
    const float* rows   = (const float*)d_in[0];
    const float* shifts = (const float*)d_in[1];
    const float* latent = (const float*)d_in[2];
    const float* coords = (const float*)d_in[3];
    const float* values = (const float*)d_in[4];
    const float* W0 = (const float*)d_in[5];
    const float* b0 = (const float*)d_in[6];
    const float* W1 = (const float*)d_in[7];
    const float* b1 = (const float*)d_in[8];
    const float* W2 = (const float*)d_in[9];
    const float* b2 = (const float*)d_in[10];
    const float* W3 = (const float*)d_in[11];
    const float* b3 = (const float*)d_in[12];
    const float* Wd = (const float*)d_in[13];
    const float* bd = (const float*)d_in[14];
    const float* ctf = (const float*)d_in[15];
    int N = in_sizes[4];

    zero_prep_kernel<<<NPIX / 4 / 256, 256>>>(rows, shifts, latent,
                                              W0, b0, W1, b1, W2, b2, W3, b3);
    scatter_kernel<<<(N + 255) / 256, 256>>>(coords, values, Wd, bd, N);
    fftA_kernel<<<BB * 32, 256>>>();
    fftB_kernel<<<BB * 33, 256>>>(ctf);
    fftD_kernel<<<BB * 32, 256>>>((float*)d_out);
}

// round 8
// speedup vs baseline: 1.2337x; 1.0333x over previous
#include <cuda_runtime.h>
#include <math.h>

#define XS   256
#define BB   16
#define HALFK 129               // XS/2 + 1
#define NPIX (BB * XS * XS)
#define SK(i) ((i) + ((i) >> 5))   // smem bank skew

// ---------------- scratch (device globals: no allocation allowed) ----------
__device__ float  g_prep[BB * 16];      // per batch: R00..R12 (6), s0, s1, h[8]
__device__ float  g_gauss[7];
__device__ float  g_img[NPIX];          // scatter target
__device__ float2 g_A[BB * XS * HALFK]; // half-spectrum [b][y/ky][kx]

// 64-thread named barrier (2 warps of one transform). ids 1..4.
__device__ __forceinline__ void barx(int id) {
    asm volatile("bar.sync %0, 64;" :: "r"(id) : "memory");
}

// ---------------- fused zero + prep + gaussian taps ----------------
__global__ void zero_prep_kernel(const float* __restrict__ rows,
                                 const float* __restrict__ shifts,
                                 const float* __restrict__ latent,
                                 const float* __restrict__ W0, const float* __restrict__ b0,
                                 const float* __restrict__ W1, const float* __restrict__ b1,
                                 const float* __restrict__ W2, const float* __restrict__ b2,
                                 const float* __restrict__ W3, const float* __restrict__ b3) {
    if (blockIdx.x == 0) {
        int b = threadIdx.x;
        if (b < BB) {
            float rot = rows[b*3+0], tilt = rows[b*3+1], psi = rows[b*3+2];
            float ca = cosf(rot),  sa = sinf(rot);
            float cb = cosf(tilt), sb = sinf(tilt);
            float cg = cosf(psi),  sg = sinf(psi);
            float nsg = -sg;
            float* p = &g_prep[b * 16];
            p[0] = __fsub_rn(__fmul_rn(__fmul_rn(cg, cb), ca), __fmul_rn(sg, sa));
            p[1] = __fadd_rn(__fmul_rn(__fmul_rn(cg, cb), sa), __fmul_rn(sg, ca));
            p[2] = -__fmul_rn(cg, sb);
            p[3] = __fsub_rn(__fmul_rn(__fmul_rn(nsg, cb), ca), __fmul_rn(cg, sa));
            p[4] = __fadd_rn(__fmul_rn(__fmul_rn(nsg, cb), sa), __fmul_rn(cg, ca));
            p[5] = __fmul_rn(sg, sb);
            p[6] = shifts[b*2+0];
            p[7] = shifts[b*2+1];

            float h[8];
            #pragma unroll
            for (int j = 0; j < 8; j++) {
                float acc = b0[j];
                #pragma unroll
                for (int l = 0; l < 8; l++) acc += latent[b*8+l] * W0[l*8+j];
                h[j] = sinf(30.0f * acc);
            }
            const float* Ws[3] = {W1, W2, W3};
            const float* bs[3] = {b1, b2, b3};
            for (int s = 0; s < 3; s++) {
                float t[8];
                #pragma unroll
                for (int j = 0; j < 8; j++) {
                    float acc = bs[s][j];
                    #pragma unroll
                    for (int l = 0; l < 8; l++) acc += h[l] * Ws[s][l*8+j];
                    t[j] = sinf(acc);
                }
                #pragma unroll
                for (int j = 0; j < 8; j++) h[j] += t[j];
            }
            #pragma unroll
            for (int j = 0; j < 8; j++) p[8+j] = h[j];
        }
        if (threadIdx.x == 0) {
            float k[7], s = 0.f;
            for (int i = 0; i < 7; i++) { float x = (float)(i - 3); k[i] = expf(-0.5f * x * x); s += k[i]; }
            for (int i = 0; i < 7; i++) g_gauss[i] = k[i] / s;
        }
    }
    int i = blockIdx.x * blockDim.x + threadIdx.x;
    float4* p4 = (float4*)g_img;
    if (i < NPIX / 4) p4[i] = make_float4(0.f, 0.f, 0.f, 0.f);
}

// ---------------- scatter (arithmetic bit-identical to passing rounds) ------
__global__ void scatter_kernel(const float* __restrict__ coords,
                               const float* __restrict__ values,
                               const float* __restrict__ Wd,
                               const float* __restrict__ bd,
                               int N) {
    __shared__ float sp[256];  // 16 batches x 16 floats
    if (threadIdx.x < 256) sp[threadIdx.x] = g_prep[threadIdx.x];
    __syncthreads();

    int n = blockIdx.x * blockDim.x + threadIdx.x;
    if (n >= N) return;

    float cx = coords[n*3+0], cy = coords[n*3+1], cz = coords[n*3+2];
    float base = values[n] + bd[n];
    float wd[8];
    #pragma unroll
    for (int l = 0; l < 8; l++) wd[l] = Wd[(size_t)l * N + n];

    #pragma unroll
    for (int b = 0; b < BB; b++) {
        const float* p = &sp[b * 16];
        float xr = __fmaf_rn(p[2], cz, __fmaf_rn(p[1], cy, __fmul_rn(p[0], cx)));
        float yr = __fmaf_rn(p[5], cz, __fmaf_rn(p[4], cy, __fmul_rn(p[3], cx)));
        float fx = rintf(__fadd_rn(__fadd_rn(xr, p[6]), 128.0f));
        float fy = rintf(__fadd_rn(__fadd_rn(yr, p[7]), 128.0f));
        fx = fminf(fmaxf(fx, 0.f), 255.f);
        fy = fminf(fmaxf(fy, 0.f), 255.f);
        int ix = (int)fx, iy = (int)fy;
        float val = base;
        #pragma unroll
        for (int l = 0; l < 8; l++) val = fmaf(p[8+l], wd[l], val);
        atomicAdd(&g_img[(b << 16) + (iy << 8) + ix], val);
    }
}

// ---------------- radix-4 Stockham 256-pt FFT (64 threads / transform) -----
// tw[k] = e^{+2pi i k/256}. sgn=-1 fwd, +1 inv (unnormalized). Result in b0.
// Per-stage sync uses a NAMED 64-thread barrier (slices are private per
// transform: skewed range [264c, 264c+263] in both buffers).
__device__ __forceinline__ float2 cmul_sgn(float2 w, float2 v, float sgn) {
    float wy = sgn * w.y;
    return make_float2(fmaf(w.x, v.x, -wy * v.y), fmaf(w.x, v.y, wy * v.x));
}

__device__ __forceinline__ void fft256_r4(float2* b0, float2* b1, const float2* tw,
                                          int o, int t, float sgn, int bid) {
    float2 *a = b0, *b = b1;
    #pragma unroll
    for (int m = 1; m < 256; m <<= 2) {
        int k = t & ~(m - 1);
        float2 c0 = a[SK(o + t)],       c1 = a[SK(o + t + 64)];
        float2 c2 = a[SK(o + t + 128)], c3 = a[SK(o + t + 192)];
        float2 t0 = make_float2(c0.x + c2.x, c0.y + c2.y);
        float2 t1 = make_float2(c0.x - c2.x, c0.y - c2.y);
        float2 t2 = make_float2(c1.x + c3.x, c1.y + c3.y);
        float2 t3 = make_float2(c1.x - c3.x, c1.y - c3.y);
        float2 u3 = make_float2(-sgn * t3.y, sgn * t3.x);   // (-+i)*t3
        float2 e0 = make_float2(t0.x + t2.x, t0.y + t2.y);
        float2 d1 = make_float2(t0.x - t2.x, t0.y - t2.y);
        float2 d2 = make_float2(t1.x + u3.x, t1.y + u3.y);
        float2 d3 = make_float2(t1.x - u3.x, t1.y - u3.y);
        int B = o + 3 * k + t;                              // o + 4k + (t-k)
        b[SK(B)]         = e0;
        b[SK(B + m)]     = cmul_sgn(tw[k],     d2, sgn);
        b[SK(B + 2*m)]   = cmul_sgn(tw[2 * k], d1, sgn);
        b[SK(B + 3*m)]   = cmul_sgn(tw[3 * k], d3, sgn);
        barx(bid);
        float2* tp = a; a = b; b = tp;
    }
}

__device__ __forceinline__ void fill_tw(float2* tw, int tid, int nthreads) {
    for (int i = tid; i < 192; i += nthreads) {
        float s, c;
        sincospif((float)i / 128.0f, &s, &c);
        tw[i] = make_float2(c, s);
    }
}

// Stage A: x-blur + forward rfft of TWO rows packed per transform.
// 256-thread block = 4 transforms = 8 rows.
__global__ void fftA_kernel() {
    __shared__ float2 buf0[1056], buf1[1056], tw[192];
    float* raw = (float*)buf1;               // 2048 floats = 8 raw rows
    int tid = threadIdx.x;
    int c = tid >> 6, t = tid & 63;
    int b  = blockIdx.x >> 5;
    int y0 = (blockIdx.x & 31) * 8;
    const float* src = &g_img[(b * 256 + y0) * 256];
    #pragma unroll
    for (int j = 0; j < 8; j++) raw[tid + j * 256] = src[tid + j * 256];
    fill_tw(tw, tid, 256);
    float w[7];
    #pragma unroll
    for (int i = 0; i < 7; i++) w[i] = g_gauss[i];
    __syncthreads();                         // raw + tw visible to all

    // x-blur rows 2c, 2c+1 (zero-padded SAME)
    float2 zz[4];
    #pragma unroll
    for (int j = 0; j < 4; j++) {
        int x = t + 64 * j;
        float a0 = 0.f, a1 = 0.f;
        #pragma unroll
        for (int d = -3; d <= 3; d++) {
            int xx = x + d;
            if (xx >= 0 && xx < 256) {
                a0 = fmaf(w[d+3], raw[(2*c)   * 256 + xx], a0);
                a1 = fmaf(w[d+3], raw[(2*c+1) * 256 + xx], a1);
            }
        }
        zz[j] = make_float2(a0, a1);
    }
    __syncthreads();                         // all raw reads before buf1 writes
    #pragma unroll
    for (int j = 0; j < 4; j++) buf0[SK(c * 256 + t + 64 * j)] = zz[j];
    // no barrier: FFT stage 1 reads exactly this thread's written elements
    fft256_r4(buf0, buf1, tw, c * 256, t, -1.0f, 1 + c);

    // Unpack packed real FFT: A1 = (Z + conj(Zr))/2 ; A2 = -i(Z - conj(Zr))/2
    float2* o1 = &g_A[(size_t)(b * 256 + y0 + 2 * c) * HALFK];
    float2* o2 = o1 + HALFK;
    #pragma unroll
    for (int j = 0; j < 2; j++) {
        int kx = t + 64 * j;
        float2 Z1 = buf0[SK(c * 256 + kx)];
        float2 Z2 = buf0[SK(c * 256 + ((256 - kx) & 255))];
        o1[kx] = make_float2(0.5f*(Z1.x + Z2.x), 0.5f*(Z1.y - Z2.y));
        o2[kx] = make_float2(0.5f*(Z1.y + Z2.y), 0.5f*(Z2.x - Z1.x));
    }
    if (t == 0) {
        float2 Zn = buf0[SK(c * 256 + 128)];
        o1[128] = make_float2(Zn.x, 0.f);
        o2[128] = make_float2(Zn.y, 0.f);
    }
}

// Stage B: y-blur + column fwd FFT + CTF + column inv FFT.
// 256-thread block = 4 kx columns (64-thread transforms). raw aliases buf1.
__global__ void fftB_kernel(const float* __restrict__ ctf) {
    __shared__ float2 buf0[1056], buf1[1056], tw[192];
    float2* raw = buf1;
    int tid = threadIdx.x;
    int c = tid >> 6, t = tid & 63;
    int b   = blockIdx.x / 33;
    int kx0 = (blockIdx.x % 33) * 4;

    #pragma unroll
    for (int r = 0; r < 4; r++) {
        int e  = tid + r * 256;
        int cc = e & 3, ky = e >> 2;
        int kx = min(kx0 + cc, 128);
        raw[cc * 256 + ky] = g_A[(size_t)(b * 256 + ky) * HALFK + kx];
    }
    fill_tw(tw, tid, 256);
    float w[7];
    #pragma unroll
    for (int i = 0; i < 7; i++) w[i] = g_gauss[i];
    __syncthreads();                         // raw + tw visible

    // y-blur (zero-padded); row index here is spatial y
    float2 zz[4];
    #pragma unroll
    for (int j = 0; j < 4; j++) {
        int y = t + 64 * j;
        float2 acc = make_float2(0.f, 0.f);
        #pragma unroll
        for (int d = -3; d <= 3; d++) {
            int yy = y + d;
            if (yy >= 0 && yy < 256) {
                float2 v = raw[c * 256 + yy];
                acc.x = fmaf(w[d+3], v.x, acc.x);
                acc.y = fmaf(w[d+3], v.y, acc.y);
            }
        }
        zz[j] = acc;
    }
    __syncthreads();                         // all raw reads before buf1 writes
    #pragma unroll
    for (int j = 0; j < 4; j++) buf0[SK(c * 256 + t + 64 * j)] = zz[j];
    // no barrier: stage-1 reads == this thread's writes
    fft256_r4(buf0, buf1, tw, c * 256, t, -1.0f, 1 + c);

    int kxc = min(kx0 + c, 128);
    #pragma unroll
    for (int j = 0; j < 4; j++) {
        int ky = t + 64 * j;
        float f = ctf[(size_t)(b * 256 + ky) * HALFK + kxc];
        float2 v = buf0[SK(c * 256 + ky)];
        buf0[SK(c * 256 + ky)] = make_float2(v.x * f, v.y * f);
    }
    // no barrier: inverse stage-1 reads == this thread's CTF writes
    fft256_r4(buf0, buf1, tw, c * 256, t, 1.0f, 1 + c);

    __syncthreads();                         // cross-transform store below
    #pragma unroll
    for (int r = 0; r < 4; r++) {
        int e  = tid + r * 256;
        int cc = e & 3, ky = e >> 2;
        int kx = kx0 + cc;
        if (kx <= 128)
            g_A[(size_t)(b * 256 + ky) * HALFK + kx] = buf0[SK(cc * 256 + ky)];
    }
}

// Stage D: inverse rfft of TWO rows per transform (S1 + i*S2 pack).
// Im of DC/Nyquist dropped (irfft semantics; keeps pack exactly Hermitian).
__global__ void fftD_kernel(float* __restrict__ out) {
    __shared__ float2 buf0[1056], buf1[1056], tw[192];
    int tid = threadIdx.x;
    int c = tid >> 6, t = tid & 63;
    int b  = blockIdx.x >> 5;
    int y0 = (blockIdx.x & 31) * 8 + 2 * c;
    const float2* A1 = &g_A[(size_t)(b * 256 + y0) * HALFK];
    const float2* A2 = A1 + HALFK;
    int o = c * 256;

    if (t == 0) {
        buf0[SK(o + 0)]   = make_float2(A1[0].x,   A2[0].x);    // Im(DC) dropped
        buf0[SK(o + 128)] = make_float2(A1[128].x, A2[128].x);  // Im(Nyq) dropped
    } else {
        float2 a1 = A1[t], a2 = A2[t];
        buf0[SK(o + t)] = make_float2(a1.x - a2.y, a1.y + a2.x);
        int m = 128 - t;                                        // j = t+128
        float2 m1 = A1[m], m2 = A2[m];
        buf0[SK(o + t + 128)] = make_float2(m1.x + m2.y, m2.x - m1.y);
    }
    {
        int j = t + 64;                                         // [64,128)
        float2 a1 = A1[j], a2 = A2[j];
        buf0[SK(o + j)] = make_float2(a1.x - a2.y, a1.y + a2.x);
    }
    {
        int m = 64 - t;                                         // j = t+192
        float2 m1 = A1[m], m2 = A2[m];
        buf0[SK(o + t + 192)] = make_float2(m1.x + m2.y, m2.x - m1.y);
    }
    fill_tw(tw, tid, 256);
    __syncthreads();                         // tw visible (pack is own-thread)
    fft256_r4(buf0, buf1, tw, o, t, 1.0f, 1 + c);

    const float s = 1.0f / 65536.0f;   // 1/(256*256)
    float* o0 = &out[(size_t)(b * 256 + y0) * 256];
    float* o1 = o0 + 256;
    #pragma unroll
    for (int j = 0; j < 4; j++) {
        float2 v = buf0[SK(o + t + 64 * j)];
        o0[t + 64 * j] = v.x * s;
        o1[t + 64 * j] = v.y * s;
    }
}

// ---------------- launch ----------------
extern "C" void kernel_launch(void* const* d_in, const int* in_sizes, int n_in,
                              void* d_out, int out_size) {
    const float* rows   = (const float*)d_in[0];
    const float* shifts = (const float*)d_in[1];
    const float* latent = (const float*)d_in[2];
    const float* coords = (const float*)d_in[3];
    const float* values = (const float*)d_in[4];
    const float* W0 = (const float*)d_in[5];
    const float* b0 = (const float*)d_in[6];
    const float* W1 = (const float*)d_in[7];
    const float* b1 = (const float*)d_in[8];
    const float* W2 = (const float*)d_in[9];
    const float* b2 = (const float*)d_in[10];
    const float* W3 = (const float*)d_in[11];
    const float* b3 = (const float*)d_in[12];
    const float* Wd = (const float*)d_in[13];
    const float* bd = (const float*)d_in[14];
    const float* ctf = (const float*)d_in[15];
    int N = in_sizes[4];

    zero_prep_kernel<<<NPIX / 4 / 256, 256>>>(rows, shifts, latent,
                                              W0, b0, W1, b1, W2, b2, W3, b3);
    scatter_kernel<<<(N + 255) / 256, 256>>>(coords, values, Wd, bd, N);
    fftA_kernel<<<BB * 32, 256>>>();
    fftB_kernel<<<BB * 33, 256>>>(ctf);
    fftD_kernel<<<BB * 32, 256>>>((float*)d_out);
}